// round 13
// baseline (speedup 1.0000x reference)
#include <cuda_runtime.h>
#include <cuda_fp16.h>
#include <math.h>
#include <stdint.h>

#define B_    32
#define C_    64
#define F_    4096
#define N_    (B_ * F_)          // 131072 tokens
#define SIZE_ 2048
#define DECAY_ 0.99f
#define OMD_   0.01f
#define EPS_   1e-5f

// ---- output layout (concatenated tuple, all float32) ----
#define OFF_Q     0
#define OFF_IDX   8388608
#define OFF_LOSS  8519680
#define OFF_NEMB  8519681
#define OFF_NCS   8650753
#define OFF_NEA   8652801

// ---- device scratch ----
// codebook, fp16 hi/lo interleaved per k-pair: [code][32 pairs][2 u32]
__device__ uint32_t g_B16[SIZE_ * 64];
__device__ float g_e2h[SIZE_];       // 0.5 * ||e||^2 (fp32)
__device__ float g_emb_sum[SIZE_ * C_];
__device__ float g_cs[SIZE_];
__device__ float g_loss;

// ---- smem layout for the fused kernel (byte offsets) ----
// P0/P1: (prologue) raw fp32 slab in P0, A fp16 layout in P1;
// (mainloop) B chunk double-buffers; (epilogue) x tile in P0.
// E2: e2 table during mainloop, idx array during epilogue.
#define SM_P0   0                 // 36864 B
#define SM_P1   36864
#define SM_E2   73728             // 2048 f32 = 8192 B
#define SM_LRED 81920             // 8 floats
#define SM_TOT  81984

__device__ __forceinline__ uint32_t smem_u32(const void* p) {
    uint32_t a;
    asm("{ .reg .u64 t; cvta.to.shared.u64 t, %1; cvt.u32.u64 %0, t; }"
        : "=r"(a) : "l"(p));
    return a;
}

__device__ __forceinline__ void cp_async16(uint32_t dst, const void* src) {
    asm volatile("cp.async.ca.shared.global [%0], [%1], 16;"
                 :: "r"(dst), "l"(src) : "memory");
}
#define CP_COMMIT() asm volatile("cp.async.commit_group;" ::: "memory")
#define CP_WAIT1()  asm volatile("cp.async.wait_group 1;"  ::: "memory")
#define CP_WAIT0()  asm volatile("cp.async.wait_group 0;"  ::: "memory")

__device__ __forceinline__ void red_add_v4(float* addr, float x, float y, float z, float w) {
    asm volatile("red.global.add.v4.f32 [%0], {%1,%2,%3,%4};"
                 :: "l"(addr), "f"(x), "f"(y), "f"(z), "f"(w) : "memory");
}

__device__ __forceinline__ void mma16816(float c[4],
                                         uint32_t a0, uint32_t a1, uint32_t a2, uint32_t a3,
                                         uint32_t b0, uint32_t b1) {
    asm volatile(
        "mma.sync.aligned.m16n8k16.row.col.f32.f16.f16.f32 "
        "{%0,%1,%2,%3}, {%4,%5,%6,%7}, {%8,%9}, {%0,%1,%2,%3};"
        : "+f"(c[0]), "+f"(c[1]), "+f"(c[2]), "+f"(c[3])
        : "r"(a0), "r"(a1), "r"(a2), "r"(a3), "r"(b0), "r"(b1));
}

// ============================================================
// Kernel 0: codebook fp16 hi/lo split + 0.5||e||^2 + zero scratch
// ============================================================
__global__ void k_init(const float* __restrict__ embedding) {
    int i = blockIdx.x * blockDim.x + threadIdx.x;   // 0..131071
    int code = i >> 6;
    int c    = i & 63;
    if ((c & 1) == 0) {
        float e0 = embedding[i];
        float e1 = embedding[i + 1];
        __half h0 = __float2half_rn(e0);
        __half h1 = __float2half_rn(e1);
        __half l0 = __float2half_rn(e0 - __half2float(h0));
        __half l1 = __float2half_rn(e1 - __half2float(h1));
        __half2 hi = __halves2half2(h0, h1);   // low half = k even
        __half2 lo = __halves2half2(l0, l1);
        int pr = c >> 1;
        g_B16[code * 64 + pr * 2]     = *(uint32_t*)&hi;
        g_B16[code * 64 + pr * 2 + 1] = *(uint32_t*)&lo;
    }
    g_emb_sum[i] = 0.0f;
    if (i < SIZE_) {
        const float* er = embedding + i * C_;
        float s = 0.0f;
#pragma unroll
        for (int k = 0; k < C_; k++) s += er[k] * er[k];
        g_e2h[i] = 0.5f * s;
        g_cs[i] = 0.0f;
    }
    if (i == 0) g_loss = 0.0f;
}

// ============================================================
// Kernel 1 (FUSED): split-fp16 mma.sync distance GEMM + argmin
// + gather/scatter/loss epilogue (overlaps other CTAs' MMA).
// R6 mainloop: 256 threads, 8 warps, M=16/warp, occ 2.
// ============================================================
__global__ void __launch_bounds__(256, 2)
k_fused(const float* __restrict__ inputs,
        const float* __restrict__ embedding,
        float* __restrict__ out) {
    extern __shared__ char sm[];
    uint32_t smb = smem_u32(sm);

    int tid = threadIdx.x;
    int w    = tid >> 5;
    int lane = tid & 31;
    int gid  = lane >> 2;
    int tig  = lane & 3;
    int b  = blockIdx.x >> 5;
    int f0 = (blockIdx.x & 31) << 7;

    // ---- stage raw fp32 slab [64 c][128 f] into P0 (coalesced) ----
    {
        const float4* inp4 = (const float4*)(inputs + (size_t)b * C_ * F_ + f0);
        float4* raw4 = (float4*)(sm + SM_P0);
#pragma unroll
        for (int it = tid; it < 2048; it += 256) {
            int c = it >> 5, m4 = it & 31;
            raw4[it] = inp4[c * (F_ / 4) + m4];
        }
    }
    // e2 table
    {
        const float4* src = (const float4*)g_e2h;
        float4* dst = (float4*)(sm + SM_E2);
#pragma unroll
        for (int it = tid; it < 512; it += 256) dst[it] = src[it];
    }
    __syncthreads();

    // ---- convert P0 raw -> P1 A fp16 hi/lo interleaved ----
    {
        const float* raw = (const float*)(sm + SM_P0);
#pragma unroll
        for (int it = tid; it < 4096; it += 256) {   // 128 m x 32 pairs
            int m = it & 127, j = it >> 7;
            float x0 = raw[(2 * j)     * 128 + m];
            float x1 = raw[(2 * j + 1) * 128 + m];
            __half h0 = __float2half_rn(x0);
            __half h1 = __float2half_rn(x1);
            __half l0 = __float2half_rn(x0 - __half2float(h0));
            __half l1 = __float2half_rn(x1 - __half2float(h1));
            __half2 hi = __halves2half2(h0, h1);
            __half2 lo = __halves2half2(l0, l1);
            uint2 v = {*(uint32_t*)&hi, *(uint32_t*)&lo};
            *(uint2*)(sm + SM_P1 + m * 288 + j * 8) = v;
        }
    }
    __syncthreads();

    // ---- load A fragments to registers ----
    uint32_t ah[16], al[16];
#pragma unroll
    for (int s = 0; s < 4; s++) {
#pragma unroll
        for (int part = 0; part < 4; part++) {
            int m  = 16 * w + gid + (part & 1) * 8;
            int pr = 8 * s + tig + (part >> 1) * 4;
            uint2 v = *(const uint2*)(sm + SM_P1 + m * 288 + pr * 8);
            ah[s * 4 + part] = v.x;
            al[s * 4 + part] = v.y;
        }
    }
    __syncthreads();   // P0/P1 now free for the B pipeline

    // ---- prologue: cp.async B chunk 0 (->P0) and 1 (->P1) ----
    const char* gB = (const char*)g_B16;
#pragma unroll
    for (int r = 0; r < 8; r++) {
        int o = tid + 256 * r;            // 0..2047
        int row = o >> 4, g = o & 15;
        cp_async16(smb + SM_P0 + row * 288 + g * 16,
                   gB + (size_t)row * 256 + g * 16);
    }
    CP_COMMIT();
#pragma unroll
    for (int r = 0; r < 8; r++) {
        int o = tid + 256 * r;
        int row = o >> 4, g = o & 15;
        cp_async16(smb + SM_P1 + row * 288 + g * 16,
                   gB + (size_t)(128 + row) * 256 + g * 16);
    }
    CP_COMMIT();

    float bestv0 = 3.4e38f, bestv1 = 3.4e38f;
    int   besti0 = 0,       besti1 = 0;

#pragma unroll 1
    for (int i = 0; i < 16; i++) {
        if (i < 14) { CP_WAIT1(); } else { CP_WAIT0(); }
        __syncthreads();
        const char* buf = sm + ((i & 1) ? SM_P1 : SM_P0);

#pragma unroll
        for (int nt = 0; nt < 16; nt++) {
            int n = nt * 8 + gid;
            const char* base = buf + n * 288;
            uint32_t bh[8], bl[8];
#pragma unroll
            for (int s = 0; s < 4; s++) {
                uint2 v0 = *(const uint2*)(base + (8 * s + tig) * 8);
                uint2 v1 = *(const uint2*)(base + (8 * s + tig + 4) * 8);
                bh[s * 2]     = v0.x;  bl[s * 2]     = v0.y;
                bh[s * 2 + 1] = v1.x;  bl[s * 2 + 1] = v1.y;
            }
            float chh[4] = {0.f, 0.f, 0.f, 0.f};
            float chl[4] = {0.f, 0.f, 0.f, 0.f};
            float clh[4] = {0.f, 0.f, 0.f, 0.f};
#pragma unroll
            for (int s = 0; s < 4; s++) {
                mma16816(chh, ah[4*s], ah[4*s+1], ah[4*s+2], ah[4*s+3], bh[2*s], bh[2*s+1]);
                mma16816(chl, ah[4*s], ah[4*s+1], ah[4*s+2], ah[4*s+3], bl[2*s], bl[2*s+1]);
                mma16816(clh, al[4*s], al[4*s+1], al[4*s+2], al[4*s+3], bh[2*s], bh[2*s+1]);
            }

            int col = i * 128 + nt * 8 + 2 * tig;
            float2 e2v = *(const float2*)(sm + SM_E2 + col * 4);
            float s0 = e2v.x - ((chh[0] + chl[0]) + clh[0]);
            float s1 = e2v.y - ((chh[1] + chl[1]) + clh[1]);
            float s2 = e2v.x - ((chh[2] + chl[2]) + clh[2]);
            float s3 = e2v.y - ((chh[3] + chl[3]) + clh[3]);
            if (s0 < bestv0) { bestv0 = s0; besti0 = col; }
            if (s1 < bestv0) { bestv0 = s1; besti0 = col + 1; }
            if (s2 < bestv1) { bestv1 = s2; besti1 = col; }
            if (s3 < bestv1) { bestv1 = s3; besti1 = col + 1; }
        }
        __syncthreads();
        if (i < 14) {
            uint32_t dstb = smb + ((i & 1) ? SM_P1 : SM_P0);
            size_t srcb = (size_t)(i + 2) * 128 * 256;
#pragma unroll
            for (int r = 0; r < 8; r++) {
                int o = tid + 256 * r;
                int row = o >> 4, g = o & 15;
                cp_async16(dstb + row * 288 + g * 16,
                           gB + srcb + (size_t)row * 256 + g * 16);
            }
            CP_COMMIT();
        }
    }

    // ---- cross-lane (quad) argmin reduce -> idx into smem ----
#pragma unroll
    for (int off = 1; off <= 2; off <<= 1) {
        float ov0 = __shfl_xor_sync(0xffffffffu, bestv0, off);
        int   oi0 = __shfl_xor_sync(0xffffffffu, besti0, off);
        float ov1 = __shfl_xor_sync(0xffffffffu, bestv1, off);
        int   oi1 = __shfl_xor_sync(0xffffffffu, besti1, off);
        if (ov0 < bestv0 || (ov0 == bestv0 && oi0 < besti0)) { bestv0 = ov0; besti0 = oi0; }
        if (ov1 < bestv1 || (ov1 == bestv1 && oi1 < besti1)) { bestv1 = ov1; besti1 = oi1; }
    }
    int* ism = (int*)(sm + SM_E2);     // e2 table dead; reuse
    if (tig == 0) {
        ism[w * 16 + gid]     = besti0;
        ism[w * 16 + gid + 8] = besti1;
    }
    __syncthreads();

    // ================= fused scatter epilogue =================
    // reload x tile [64 c][128 f] into P0 (free after mainloop)
    float* xs = (float*)(sm + SM_P0);
    float4* xs4 = (float4*)xs;
    {
        const float4* inp4 = (const float4*)(inputs + (size_t)b * C_ * F_ + f0);
#pragma unroll
        for (int it = tid; it < 2048; it += 256) {
            int c = it >> 5, m4 = it & 31;
            xs4[it] = inp4[c * (F_ / 4) + m4];
        }
    }
    __syncthreads();

    float* lred = (float*)(sm + SM_LRED);
    float lacc = 0.0f;
    if (tid < 128) {
        int t = b * F_ + f0 + tid;
        int idx = ism[tid];
        const float4* e4 = (const float4*)(embedding + idx * C_);
        float* esum = g_emb_sum + (size_t)idx * C_;
#pragma unroll
        for (int c4 = 0; c4 < 16; c4++) {
            float4 q = e4[c4];
            float qv[4] = {q.x, q.y, q.z, q.w};
            float xv[4];
#pragma unroll
            for (int l = 0; l < 4; l++) {
                int c = c4 * 4 + l;
                float x = xs[c * 128 + tid];
                xv[l] = x;
                float d = x - qv[l];
                lacc = fmaf(d, d, lacc);
                xs[c * 128 + tid] = qv[l];
            }
            red_add_v4(&esum[c4 * 4], xv[0], xv[1], xv[2], xv[3]);
        }
        atomicAdd(&g_cs[idx], 1.0f);
        out[OFF_IDX + t] = (float)idx;
    }
#pragma unroll
    for (int off = 16; off > 0; off >>= 1)
        lacc += __shfl_down_sync(0xffffffffu, lacc, off);
    if (lane == 0) lred[w] = lacc;
    __syncthreads();
    if (tid == 0)
        atomicAdd(&g_loss, ((lred[0] + lred[1]) + (lred[2] + lred[3])));

    // write quantized tile [b][c][f0..f0+128) coalesced
    float4* out4 = (float4*)(out + OFF_Q);
    size_t rowbase = (size_t)b * C_ * F_;
#pragma unroll
    for (int it = tid; it < 2048; it += 256) {
        int c = it >> 5, m4 = it & 31;
        out4[(rowbase + (size_t)c * F_ + f0) / 4 + m4] = xs4[it];
    }
}

// ============================================================
// Kernel 2 (merged EMA): every block re-reduces n over 2048 codes,
// computes its slice of new_embedding_avg / new_embedding; block 0
// also writes new_cluster_size + loss.  512 blocks x 256 threads.
// ============================================================
__global__ void __launch_bounds__(256)
k_ema(const float* __restrict__ embedding_avg,
      const float* __restrict__ cluster_size,
      float* __restrict__ out) {
    __shared__ float wsum[8];
    __shared__ float s_n;
    int tid = threadIdx.x;

    float s = 0.0f;
#pragma unroll
    for (int k = 0; k < 8; k++) {
        int j = tid + 256 * k;
        s += DECAY_ * cluster_size[j] + OMD_ * g_cs[j];
    }
#pragma unroll
    for (int off = 16; off > 0; off >>= 1)
        s += __shfl_down_sync(0xffffffffu, s, off);
    if ((tid & 31) == 0) wsum[tid >> 5] = s;
    __syncthreads();
    if (tid == 0) {
        float n = 0.0f;
#pragma unroll
        for (int w = 0; w < 8; w++) n += wsum[w];
        s_n = n;
    }
    __syncthreads();
    float n = s_n;
    float denom = n + (float)SIZE_ * EPS_;
    float mn = fmaxf(n, 1.0f);

    if (blockIdx.x == 0) {
#pragma unroll
        for (int k = 0; k < 8; k++) {
            int j = tid + 256 * k;
            out[OFF_NCS + j] = DECAY_ * cluster_size[j] + OMD_ * g_cs[j];
        }
        if (tid == 0)
            out[OFF_LOSS] = g_loss * (1.0f / (float)(N_ * C_));
    }

    int i = blockIdx.x * 256 + tid;           // 0..131071
    int row = i >> 6;
    float ncs = DECAY_ * cluster_size[row] + OMD_ * g_cs[row];
    float inv = denom / ((ncs + EPS_) * mn);
    float nea = DECAY_ * embedding_avg[i] + OMD_ * g_emb_sum[i];
    out[OFF_NEA + i]  = nea;
    out[OFF_NEMB + i] = nea * inv;
}

// ============================================================
extern "C" void kernel_launch(void* const* d_in, const int* in_sizes, int n_in,
                              void* d_out, int out_size) {
    const float* inputs        = (const float*)d_in[0];
    const float* embedding     = (const float*)d_in[1];
    const float* embedding_avg = (const float*)d_in[2];
    const float* cluster_size  = (const float*)d_in[3];
    float* out = (float*)d_out;

    cudaFuncSetAttribute(k_fused, cudaFuncAttributeMaxDynamicSharedMemorySize, SM_TOT);

    k_init<<<512, 256>>>(embedding);
    k_fused<<<1024, 256, SM_TOT>>>(inputs, embedding, out);
    k_ema<<<512, 256>>>(embedding_avg, cluster_size, out);
}

// round 14
// speedup vs baseline: 1.0566x; 1.0566x over previous
#include <cuda_runtime.h>
#include <cuda_fp16.h>
#include <math.h>
#include <stdint.h>

#define B_    32
#define C_    64
#define F_    4096
#define N_    (B_ * F_)          // 131072 tokens
#define SIZE_ 2048
#define DECAY_ 0.99f
#define OMD_   0.01f
#define EPS_   1e-5f

// ---- output layout (concatenated tuple, all float32) ----
#define OFF_Q     0
#define OFF_IDX   8388608
#define OFF_LOSS  8519680
#define OFF_NEMB  8519681
#define OFF_NCS   8650753
#define OFF_NEA   8652801

// ---- device scratch ----
// codebook, fp16 hi/lo interleaved per k-pair: [code][32 pairs][2 u32]
__device__ uint32_t g_B16[SIZE_ * 64];
__device__ float g_e2p[SIZE_ * 2];   // per-half-code sum of squares
__device__ int   g_idx[N_];
__device__ float g_emb_sum[SIZE_ * C_];
__device__ float g_cs[SIZE_];
__device__ float g_loss;

// ---- smem layout for the GEMM kernel (byte offsets) ----
// P0/P1 double as: (prologue) raw fp32 slab in P0, A fp16 layout in P1;
// (mainloop) B chunk double-buffers (288B row stride, uint2 access).
#define SM_P0   0                 // 36864 B
#define SM_P1   36864
#define SM_E2   73728             // 2048 f32 = 8192 B
#define SM_TOT  81920

__device__ __forceinline__ uint32_t smem_u32(const void* p) {
    uint32_t a;
    asm("{ .reg .u64 t; cvta.to.shared.u64 t, %1; cvt.u32.u64 %0, t; }"
        : "=r"(a) : "l"(p));
    return a;
}

__device__ __forceinline__ void cp_async16(uint32_t dst, const void* src) {
    asm volatile("cp.async.ca.shared.global [%0], [%1], 16;"
                 :: "r"(dst), "l"(src) : "memory");
}
#define CP_COMMIT() asm volatile("cp.async.commit_group;" ::: "memory")
#define CP_WAIT1()  asm volatile("cp.async.wait_group 1;"  ::: "memory")
#define CP_WAIT0()  asm volatile("cp.async.wait_group 0;"  ::: "memory")

__device__ __forceinline__ void red_add_v4(float* addr, float x, float y, float z, float w) {
    asm volatile("red.global.add.v4.f32 [%0], {%1,%2,%3,%4};"
                 :: "l"(addr), "f"(x), "f"(y), "f"(z), "f"(w) : "memory");
}

__device__ __forceinline__ void mma16816(float c[4],
                                         uint32_t a0, uint32_t a1, uint32_t a2, uint32_t a3,
                                         uint32_t b0, uint32_t b1) {
    asm volatile(
        "mma.sync.aligned.m16n8k16.row.col.f32.f16.f16.f32 "
        "{%0,%1,%2,%3}, {%4,%5,%6,%7}, {%8,%9}, {%0,%1,%2,%3};"
        : "+f"(c[0]), "+f"(c[1]), "+f"(c[2]), "+f"(c[3])
        : "r"(a0), "r"(a1), "r"(a2), "r"(a3), "r"(b0), "r"(b1));
}

// ============================================================
// Kernel 0: codebook fp16 hi/lo split + e2 partials (warp reduce)
// (R10 init: coalesced, latency-free)
// ============================================================
__global__ void k_init(const float* __restrict__ embedding) {
    int i = blockIdx.x * blockDim.x + threadIdx.x;   // 0..131071
    int c = i & 63;
    float p = 0.0f;
    if ((c & 1) == 0) {
        int code = i >> 6;
        float e0 = embedding[i];
        float e1 = embedding[i + 1];
        p = e0 * e0 + e1 * e1;
        __half h0 = __float2half_rn(e0);
        __half h1 = __float2half_rn(e1);
        __half l0 = __float2half_rn(e0 - __half2float(h0));
        __half l1 = __float2half_rn(e1 - __half2float(h1));
        __half2 hi = __halves2half2(h0, h1);   // low half = k even
        __half2 lo = __halves2half2(l0, l1);
        int pr = c >> 1;
        g_B16[code * 64 + pr * 2]     = *(uint32_t*)&hi;
        g_B16[code * 64 + pr * 2 + 1] = *(uint32_t*)&lo;
    }
    // warp covers elements [i&~31, (i&~31)+32) = half of one code
#pragma unroll
    for (int off = 16; off > 0; off >>= 1)
        p += __shfl_down_sync(0xffffffffu, p, off);
    if ((i & 31) == 0) g_e2p[i >> 5] = p;

    g_emb_sum[i] = 0.0f;
    if (i < SIZE_) g_cs[i] = 0.0f;
    if (i == 0) g_loss = 0.0f;
}

// ============================================================
// Kernel 1: split-fp16 mma.sync distance GEMM + fused argmin
// (R6 winner: 256 threads, 8 warps, M=16/warp, occ 2)
// ============================================================
__global__ void __launch_bounds__(256, 2)
k_argmin_mma(const float* __restrict__ inputs) {
    extern __shared__ char sm[];
    uint32_t smb = smem_u32(sm);

    int tid = threadIdx.x;
    int w    = tid >> 5;
    int lane = tid & 31;
    int gid  = lane >> 2;
    int tig  = lane & 3;
    int b  = blockIdx.x >> 5;
    int f0 = (blockIdx.x & 31) << 7;

    // ---- stage raw fp32 slab [64 c][128 f] into P0 (coalesced) ----
    {
        const float4* inp4 = (const float4*)(inputs + (size_t)b * C_ * F_ + f0);
        float4* raw4 = (float4*)(sm + SM_P0);
#pragma unroll
        for (int it = tid; it < 2048; it += 256) {
            int c = it >> 5, m4 = it & 31;
            raw4[it] = inp4[c * (F_ / 4) + m4];
        }
    }
    // e2 table: 0.5 * (part[2c] + part[2c+1])
    {
        const float2* src = (const float2*)g_e2p;
        float* dst = (float*)(sm + SM_E2);
#pragma unroll
        for (int c = tid; c < 2048; c += 256) {
            float2 v = src[c];
            dst[c] = 0.5f * (v.x + v.y);
        }
    }
    __syncthreads();

    // ---- convert P0 raw -> P1 A fp16 hi/lo interleaved ----
    {
        const float* raw = (const float*)(sm + SM_P0);
#pragma unroll
        for (int it = tid; it < 4096; it += 256) {   // 128 m x 32 pairs
            int m = it & 127, j = it >> 7;
            float x0 = raw[(2 * j)     * 128 + m];
            float x1 = raw[(2 * j + 1) * 128 + m];
            __half h0 = __float2half_rn(x0);
            __half h1 = __float2half_rn(x1);
            __half l0 = __float2half_rn(x0 - __half2float(h0));
            __half l1 = __float2half_rn(x1 - __half2float(h1));
            __half2 hi = __halves2half2(h0, h1);
            __half2 lo = __halves2half2(l0, l1);
            uint2 v = {*(uint32_t*)&hi, *(uint32_t*)&lo};
            *(uint2*)(sm + SM_P1 + m * 288 + j * 8) = v;
        }
    }
    __syncthreads();

    // ---- load A fragments to registers ----
    uint32_t ah[16], al[16];
#pragma unroll
    for (int s = 0; s < 4; s++) {
#pragma unroll
        for (int part = 0; part < 4; part++) {
            int m  = 16 * w + gid + (part & 1) * 8;
            int pr = 8 * s + tig + (part >> 1) * 4;
            uint2 v = *(const uint2*)(sm + SM_P1 + m * 288 + pr * 8);
            ah[s * 4 + part] = v.x;
            al[s * 4 + part] = v.y;
        }
    }
    __syncthreads();   // P0/P1 now free for the B pipeline

    // ---- prologue: cp.async B chunk 0 (->P0) and 1 (->P1) ----
    const char* gB = (const char*)g_B16;
#pragma unroll
    for (int r = 0; r < 8; r++) {
        int o = tid + 256 * r;            // 0..2047
        int row = o >> 4, g = o & 15;
        cp_async16(smb + SM_P0 + row * 288 + g * 16,
                   gB + (size_t)row * 256 + g * 16);
    }
    CP_COMMIT();
#pragma unroll
    for (int r = 0; r < 8; r++) {
        int o = tid + 256 * r;
        int row = o >> 4, g = o & 15;
        cp_async16(smb + SM_P1 + row * 288 + g * 16,
                   gB + (size_t)(128 + row) * 256 + g * 16);
    }
    CP_COMMIT();

    float bestv0 = 3.4e38f, bestv1 = 3.4e38f;
    int   besti0 = 0,       besti1 = 0;

#pragma unroll 1
    for (int i = 0; i < 16; i++) {
        if (i < 14) { CP_WAIT1(); } else { CP_WAIT0(); }
        __syncthreads();
        const char* buf = sm + ((i & 1) ? SM_P1 : SM_P0);

#pragma unroll
        for (int nt = 0; nt < 16; nt++) {
            int n = nt * 8 + gid;
            const char* base = buf + n * 288;
            uint32_t bh[8], bl[8];
#pragma unroll
            for (int s = 0; s < 4; s++) {
                uint2 v0 = *(const uint2*)(base + (8 * s + tig) * 8);
                uint2 v1 = *(const uint2*)(base + (8 * s + tig + 4) * 8);
                bh[s * 2]     = v0.x;  bl[s * 2]     = v0.y;
                bh[s * 2 + 1] = v1.x;  bl[s * 2 + 1] = v1.y;
            }
            float chh[4] = {0.f, 0.f, 0.f, 0.f};
            float chl[4] = {0.f, 0.f, 0.f, 0.f};
            float clh[4] = {0.f, 0.f, 0.f, 0.f};
#pragma unroll
            for (int s = 0; s < 4; s++) {
                mma16816(chh, ah[4*s], ah[4*s+1], ah[4*s+2], ah[4*s+3], bh[2*s], bh[2*s+1]);
                mma16816(chl, ah[4*s], ah[4*s+1], ah[4*s+2], ah[4*s+3], bl[2*s], bl[2*s+1]);
                mma16816(clh, al[4*s], al[4*s+1], al[4*s+2], al[4*s+3], bh[2*s], bh[2*s+1]);
            }

            int col = i * 128 + nt * 8 + 2 * tig;
            float2 e2v = *(const float2*)(sm + SM_E2 + col * 4);
            float s0 = e2v.x - ((chh[0] + chl[0]) + clh[0]);
            float s1 = e2v.y - ((chh[1] + chl[1]) + clh[1]);
            float s2 = e2v.x - ((chh[2] + chl[2]) + clh[2]);
            float s3 = e2v.y - ((chh[3] + chl[3]) + clh[3]);
            if (s0 < bestv0) { bestv0 = s0; besti0 = col; }
            if (s1 < bestv0) { bestv0 = s1; besti0 = col + 1; }
            if (s2 < bestv1) { bestv1 = s2; besti1 = col; }
            if (s3 < bestv1) { bestv1 = s3; besti1 = col + 1; }
        }
        __syncthreads();
        if (i < 14) {
            uint32_t dstb = smb + ((i & 1) ? SM_P1 : SM_P0);
            size_t srcb = (size_t)(i + 2) * 128 * 256;
#pragma unroll
            for (int r = 0; r < 8; r++) {
                int o = tid + 256 * r;
                int row = o >> 4, g = o & 15;
                cp_async16(dstb + row * 288 + g * 16,
                           gB + srcb + (size_t)row * 256 + g * 16);
            }
            CP_COMMIT();
        }
    }

    // ---- cross-lane (quad) argmin reduce, then store ----
#pragma unroll
    for (int off = 1; off <= 2; off <<= 1) {
        float ov0 = __shfl_xor_sync(0xffffffffu, bestv0, off);
        int   oi0 = __shfl_xor_sync(0xffffffffu, besti0, off);
        float ov1 = __shfl_xor_sync(0xffffffffu, bestv1, off);
        int   oi1 = __shfl_xor_sync(0xffffffffu, besti1, off);
        if (ov0 < bestv0 || (ov0 == bestv0 && oi0 < besti0)) { bestv0 = ov0; besti0 = oi0; }
        if (ov1 < bestv1 || (ov1 == bestv1 && oi1 < besti1)) { bestv1 = ov1; besti1 = oi1; }
    }
    if (tig == 0) {
        int tok = b * F_ + f0 + w * 16 + gid;
        g_idx[tok]     = besti0;
        g_idx[tok + 8] = besti1;
    }
}

// ============================================================
// Kernel 2: gather quantized + scatter segment sums (red.v4) + loss
// ============================================================
__global__ void __launch_bounds__(128)
k_scatter(const float* __restrict__ inputs,
          const float* __restrict__ embedding,
          float* __restrict__ out) {
    __shared__ float xs[C_ * 128];
    float4* xs4 = (float4*)xs;

    int tid = threadIdx.x;
    int b  = blockIdx.x >> 5;
    int f0 = (blockIdx.x & 31) << 7;

    const float4* inp4 = (const float4*)(inputs + (size_t)b * C_ * F_);
    int f04 = f0 >> 2;
#pragma unroll
    for (int it = tid; it < 2048; it += 128) {
        int k = it >> 5, m4 = it & 31;
        xs4[it] = inp4[k * (F_ / 4) + f04 + m4];
    }
    __syncthreads();

    int t = b * F_ + f0 + tid;
    int idx = g_idx[t];
    const float4* e4 = (const float4*)(embedding + idx * C_);
    float* esum = g_emb_sum + (size_t)idx * C_;

    float lacc = 0.0f;
#pragma unroll
    for (int c4 = 0; c4 < 16; c4++) {
        float4 q = e4[c4];
        float qv[4] = {q.x, q.y, q.z, q.w};
        float xv[4];
#pragma unroll
        for (int l = 0; l < 4; l++) {
            int c = c4 * 4 + l;
            float x = xs[c * 128 + tid];
            xv[l] = x;
            float d = x - qv[l];
            lacc = fmaf(d, d, lacc);
            xs[c * 128 + tid] = qv[l];
        }
        red_add_v4(&esum[c4 * 4], xv[0], xv[1], xv[2], xv[3]);
    }
    atomicAdd(&g_cs[idx], 1.0f);
    out[OFF_IDX + t] = (float)idx;

#pragma unroll
    for (int off = 16; off > 0; off >>= 1)
        lacc += __shfl_down_sync(0xffffffffu, lacc, off);
    if ((tid & 31) == 0) atomicAdd(&g_loss, lacc);

    __syncthreads();
    float4* out4 = (float4*)(out + OFF_Q);
    size_t rowbase = (size_t)b * C_ * F_;
#pragma unroll
    for (int it = tid; it < 2048; it += 128) {
        int c = it >> 5, m4 = it & 31;
        out4[(rowbase + (size_t)c * F_ + f0) / 4 + m4] = xs4[it];
    }
}

// ============================================================
// Kernel 3 (merged EMA): every block re-reduces n over 2048 codes,
// computes its slice of new_embedding_avg / new_embedding; block 0
// also writes new_cluster_size + loss.  512 blocks x 256 threads.
// ============================================================
__global__ void __launch_bounds__(256)
k_ema(const float* __restrict__ embedding_avg,
      const float* __restrict__ cluster_size,
      float* __restrict__ out) {
    __shared__ float wsum[8];
    __shared__ float s_n;
    int tid = threadIdx.x;

    float s = 0.0f;
#pragma unroll
    for (int k = 0; k < 8; k++) {
        int j = tid + 256 * k;
        s += DECAY_ * cluster_size[j] + OMD_ * g_cs[j];
    }
#pragma unroll
    for (int off = 16; off > 0; off >>= 1)
        s += __shfl_down_sync(0xffffffffu, s, off);
    if ((tid & 31) == 0) wsum[tid >> 5] = s;
    __syncthreads();
    if (tid == 0) {
        float n = 0.0f;
#pragma unroll
        for (int w = 0; w < 8; w++) n += wsum[w];
        s_n = n;
    }
    __syncthreads();
    float n = s_n;
    float denom = n + (float)SIZE_ * EPS_;
    float mn = fmaxf(n, 1.0f);

    if (blockIdx.x == 0) {
#pragma unroll
        for (int k = 0; k < 8; k++) {
            int j = tid + 256 * k;
            out[OFF_NCS + j] = DECAY_ * cluster_size[j] + OMD_ * g_cs[j];
        }
        if (tid == 0)
            out[OFF_LOSS] = g_loss * (1.0f / (float)(N_ * C_));
    }

    int i = blockIdx.x * 256 + tid;           // 0..131071
    int row = i >> 6;
    float ncs = DECAY_ * cluster_size[row] + OMD_ * g_cs[row];
    float inv = denom / ((ncs + EPS_) * mn);
    float nea = DECAY_ * embedding_avg[i] + OMD_ * g_emb_sum[i];
    out[OFF_NEA + i]  = nea;
    out[OFF_NEMB + i] = nea * inv;
}

// ============================================================
extern "C" void kernel_launch(void* const* d_in, const int* in_sizes, int n_in,
                              void* d_out, int out_size) {
    const float* inputs        = (const float*)d_in[0];
    const float* embedding     = (const float*)d_in[1];
    const float* embedding_avg = (const float*)d_in[2];
    const float* cluster_size  = (const float*)d_in[3];
    float* out = (float*)d_out;

    cudaFuncSetAttribute(k_argmin_mma, cudaFuncAttributeMaxDynamicSharedMemorySize, SM_TOT);

    k_init<<<512, 256>>>(embedding);
    k_argmin_mma<<<1024, 256, SM_TOT>>>(inputs);
    k_scatter<<<1024, 128>>>(inputs, embedding, out);
    k_ema<<<512, 256>>>(embedding_avg, cluster_size, out);
}

// round 15
// speedup vs baseline: 1.0719x; 1.0145x over previous
#include <cuda_runtime.h>
#include <cuda_fp16.h>
#include <math.h>
#include <stdint.h>

#define B_    32
#define C_    64
#define F_    4096
#define N_    (B_ * F_)          // 131072 tokens
#define SIZE_ 2048
#define DECAY_ 0.99f
#define OMD_   0.01f
#define EPS_   1e-5f

// ---- output layout (concatenated tuple, all float32) ----
#define OFF_Q     0
#define OFF_IDX   8388608
#define OFF_LOSS  8519680
#define OFF_NEMB  8519681
#define OFF_NCS   8650753
#define OFF_NEA   8652801

// ---- device scratch ----
// codebook, fp16 hi/lo interleaved per k-pair: [code][32 pairs][2 u32]
__device__ uint32_t g_B16[SIZE_ * 64];
__device__ float g_e2p[SIZE_ * 2];   // per-half-code sum of squares
__device__ int   g_idx[N_];
__device__ float g_emb_sum[SIZE_ * C_];
__device__ float g_cs[SIZE_];
__device__ float g_loss;

// ---- smem layout for the GEMM kernel (byte offsets) ----
#define SM_P0   0                 // 36864 B
#define SM_P1   36864
#define SM_E2   73728             // 2048 f32 = 8192 B
#define SM_TOT  81920

__device__ __forceinline__ uint32_t smem_u32(const void* p) {
    uint32_t a;
    asm("{ .reg .u64 t; cvta.to.shared.u64 t, %1; cvt.u32.u64 %0, t; }"
        : "=r"(a) : "l"(p));
    return a;
}

__device__ __forceinline__ void cp_async16(uint32_t dst, const void* src) {
    asm volatile("cp.async.ca.shared.global [%0], [%1], 16;"
                 :: "r"(dst), "l"(src) : "memory");
}
#define CP_COMMIT() asm volatile("cp.async.commit_group;" ::: "memory")
#define CP_WAIT1()  asm volatile("cp.async.wait_group 1;"  ::: "memory")
#define CP_WAIT0()  asm volatile("cp.async.wait_group 0;"  ::: "memory")

__device__ __forceinline__ void red_add_v4(float* addr, float x, float y, float z, float w) {
    asm volatile("red.global.add.v4.f32 [%0], {%1,%2,%3,%4};"
                 :: "l"(addr), "f"(x), "f"(y), "f"(z), "f"(w) : "memory");
}

__device__ __forceinline__ void mma16816_f32(float c[4],
                                             uint32_t a0, uint32_t a1, uint32_t a2, uint32_t a3,
                                             uint32_t b0, uint32_t b1) {
    asm volatile(
        "mma.sync.aligned.m16n8k16.row.col.f32.f16.f16.f32 "
        "{%0,%1,%2,%3}, {%4,%5,%6,%7}, {%8,%9}, {%0,%1,%2,%3};"
        : "+f"(c[0]), "+f"(c[1]), "+f"(c[2]), "+f"(c[3])
        : "r"(a0), "r"(a1), "r"(a2), "r"(a3), "r"(b0), "r"(b1));
}
__device__ __forceinline__ void mma16816_f16(uint32_t c[2],
                                             uint32_t a0, uint32_t a1, uint32_t a2, uint32_t a3,
                                             uint32_t b0, uint32_t b1) {
    asm volatile(
        "mma.sync.aligned.m16n8k16.row.col.f16.f16.f16.f16 "
        "{%0,%1}, {%2,%3,%4,%5}, {%6,%7}, {%0,%1};"
        : "+r"(c[0]), "+r"(c[1])
        : "r"(a0), "r"(a1), "r"(a2), "r"(a3), "r"(b0), "r"(b1));
}

// ============================================================
// Kernel 0: codebook fp16 hi/lo split + e2 partials (warp reduce)
// ============================================================
__global__ void k_init(const float* __restrict__ embedding) {
    int i = blockIdx.x * blockDim.x + threadIdx.x;   // 0..131071
    int c = i & 63;
    float p = 0.0f;
    if ((c & 1) == 0) {
        int code = i >> 6;
        float e0 = embedding[i];
        float e1 = embedding[i + 1];
        p = e0 * e0 + e1 * e1;
        __half h0 = __float2half_rn(e0);
        __half h1 = __float2half_rn(e1);
        __half l0 = __float2half_rn(e0 - __half2float(h0));
        __half l1 = __float2half_rn(e1 - __half2float(h1));
        __half2 hi = __halves2half2(h0, h1);   // low half = k even
        __half2 lo = __halves2half2(l0, l1);
        int pr = c >> 1;
        g_B16[code * 64 + pr * 2]     = *(uint32_t*)&hi;
        g_B16[code * 64 + pr * 2 + 1] = *(uint32_t*)&lo;
    }
#pragma unroll
    for (int off = 16; off > 0; off >>= 1)
        p += __shfl_down_sync(0xffffffffu, p, off);
    if ((i & 31) == 0) g_e2p[i >> 5] = p;

    g_emb_sum[i] = 0.0f;
    if (i < SIZE_) g_cs[i] = 0.0f;
    if (i == 0) g_loss = 0.0f;
}

// ============================================================
// Kernel 1: split-fp16 mma.sync distance GEMM + fused argmin
// R14 structure; chl/clh switched to f16-accumulate MMAs (rate test).
// ============================================================
__global__ void __launch_bounds__(256, 2)
k_argmin_mma(const float* __restrict__ inputs) {
    extern __shared__ char sm[];
    uint32_t smb = smem_u32(sm);

    int tid = threadIdx.x;
    int w    = tid >> 5;
    int lane = tid & 31;
    int gid  = lane >> 2;
    int tig  = lane & 3;
    int b  = blockIdx.x >> 5;
    int f0 = (blockIdx.x & 31) << 7;

    // ---- stage raw fp32 slab [64 c][128 f] into P0 (coalesced) ----
    {
        const float4* inp4 = (const float4*)(inputs + (size_t)b * C_ * F_ + f0);
        float4* raw4 = (float4*)(sm + SM_P0);
#pragma unroll
        for (int it = tid; it < 2048; it += 256) {
            int c = it >> 5, m4 = it & 31;
            raw4[it] = inp4[c * (F_ / 4) + m4];
        }
    }
    // e2 table: 0.5 * (part[2c] + part[2c+1])
    {
        const float2* src = (const float2*)g_e2p;
        float* dst = (float*)(sm + SM_E2);
#pragma unroll
        for (int c = tid; c < 2048; c += 256) {
            float2 v = src[c];
            dst[c] = 0.5f * (v.x + v.y);
        }
    }
    __syncthreads();

    // ---- convert P0 raw -> P1 A fp16 hi/lo interleaved ----
    {
        const float* raw = (const float*)(sm + SM_P0);
#pragma unroll
        for (int it = tid; it < 4096; it += 256) {   // 128 m x 32 pairs
            int m = it & 127, j = it >> 7;
            float x0 = raw[(2 * j)     * 128 + m];
            float x1 = raw[(2 * j + 1) * 128 + m];
            __half h0 = __float2half_rn(x0);
            __half h1 = __float2half_rn(x1);
            __half l0 = __float2half_rn(x0 - __half2float(h0));
            __half l1 = __float2half_rn(x1 - __half2float(h1));
            __half2 hi = __halves2half2(h0, h1);
            __half2 lo = __halves2half2(l0, l1);
            uint2 v = {*(uint32_t*)&hi, *(uint32_t*)&lo};
            *(uint2*)(sm + SM_P1 + m * 288 + j * 8) = v;
        }
    }
    __syncthreads();

    // ---- load A fragments to registers ----
    uint32_t ah[16], al[16];
#pragma unroll
    for (int s = 0; s < 4; s++) {
#pragma unroll
        for (int part = 0; part < 4; part++) {
            int m  = 16 * w + gid + (part & 1) * 8;
            int pr = 8 * s + tig + (part >> 1) * 4;
            uint2 v = *(const uint2*)(sm + SM_P1 + m * 288 + pr * 8);
            ah[s * 4 + part] = v.x;
            al[s * 4 + part] = v.y;
        }
    }
    __syncthreads();   // P0/P1 now free for the B pipeline

    // ---- prologue: cp.async B chunk 0 (->P0) and 1 (->P1) ----
    const char* gB = (const char*)g_B16;
#pragma unroll
    for (int r = 0; r < 8; r++) {
        int o = tid + 256 * r;            // 0..2047
        int row = o >> 4, g = o & 15;
        cp_async16(smb + SM_P0 + row * 288 + g * 16,
                   gB + (size_t)row * 256 + g * 16);
    }
    CP_COMMIT();
#pragma unroll
    for (int r = 0; r < 8; r++) {
        int o = tid + 256 * r;
        int row = o >> 4, g = o & 15;
        cp_async16(smb + SM_P1 + row * 288 + g * 16,
                   gB + (size_t)(128 + row) * 256 + g * 16);
    }
    CP_COMMIT();

    float bestv0 = 3.4e38f, bestv1 = 3.4e38f;
    int   besti0 = 0,       besti1 = 0;

#pragma unroll 1
    for (int i = 0; i < 16; i++) {
        if (i < 14) { CP_WAIT1(); } else { CP_WAIT0(); }
        __syncthreads();
        const char* buf = sm + ((i & 1) ? SM_P1 : SM_P0);

#pragma unroll
        for (int nt = 0; nt < 16; nt++) {
            int n = nt * 8 + gid;
            const char* base = buf + n * 288;
            uint32_t bh[8], bl[8];
#pragma unroll
            for (int s = 0; s < 4; s++) {
                uint2 v0 = *(const uint2*)(base + (8 * s + tig) * 8);
                uint2 v1 = *(const uint2*)(base + (8 * s + tig + 4) * 8);
                bh[s * 2]     = v0.x;  bl[s * 2]     = v0.y;
                bh[s * 2 + 1] = v1.x;  bl[s * 2 + 1] = v1.y;
            }
            float    chh[4] = {0.f, 0.f, 0.f, 0.f};
            uint32_t chl[2] = {0u, 0u};
            uint32_t clh[2] = {0u, 0u};
#pragma unroll
            for (int s = 0; s < 4; s++) {
                mma16816_f32(chh, ah[4*s], ah[4*s+1], ah[4*s+2], ah[4*s+3], bh[2*s], bh[2*s+1]);
                mma16816_f16(chl, ah[4*s], ah[4*s+1], ah[4*s+2], ah[4*s+3], bl[2*s], bl[2*s+1]);
                mma16816_f16(clh, al[4*s], al[4*s+1], al[4*s+2], al[4*s+3], bh[2*s], bh[2*s+1]);
            }

            int col = i * 128 + nt * 8 + 2 * tig;
            float2 e2v = *(const float2*)(sm + SM_E2 + col * 4);
            __half2 lo0 = __hadd2(*(__half2*)&chl[0], *(__half2*)&clh[0]);
            __half2 lo1 = __hadd2(*(__half2*)&chl[1], *(__half2*)&clh[1]);
            float2 f0v = __half22float2(lo0);
            float2 f1v = __half22float2(lo1);
            float s0 = e2v.x - (chh[0] + f0v.x);
            float s1 = e2v.y - (chh[1] + f0v.y);
            float s2 = e2v.x - (chh[2] + f1v.x);
            float s3 = e2v.y - (chh[3] + f1v.y);
            if (s0 < bestv0) { bestv0 = s0; besti0 = col; }
            if (s1 < bestv0) { bestv0 = s1; besti0 = col + 1; }
            if (s2 < bestv1) { bestv1 = s2; besti1 = col; }
            if (s3 < bestv1) { bestv1 = s3; besti1 = col + 1; }
        }
        __syncthreads();
        if (i < 14) {
            uint32_t dstb = smb + ((i & 1) ? SM_P1 : SM_P0);
            size_t srcb = (size_t)(i + 2) * 128 * 256;
#pragma unroll
            for (int r = 0; r < 8; r++) {
                int o = tid + 256 * r;
                int row = o >> 4, g = o & 15;
                cp_async16(dstb + row * 288 + g * 16,
                           gB + srcb + (size_t)row * 256 + g * 16);
            }
            CP_COMMIT();
        }
    }

    // ---- cross-lane (quad) argmin reduce, then store ----
#pragma unroll
    for (int off = 1; off <= 2; off <<= 1) {
        float ov0 = __shfl_xor_sync(0xffffffffu, bestv0, off);
        int   oi0 = __shfl_xor_sync(0xffffffffu, besti0, off);
        float ov1 = __shfl_xor_sync(0xffffffffu, bestv1, off);
        int   oi1 = __shfl_xor_sync(0xffffffffu, besti1, off);
        if (ov0 < bestv0 || (ov0 == bestv0 && oi0 < besti0)) { bestv0 = ov0; besti0 = oi0; }
        if (ov1 < bestv1 || (ov1 == bestv1 && oi1 < besti1)) { bestv1 = ov1; besti1 = oi1; }
    }
    if (tig == 0) {
        int tok = b * F_ + f0 + w * 16 + gid;
        g_idx[tok]     = besti0;
        g_idx[tok + 8] = besti1;
    }
}

// ============================================================
// Kernel 2: gather quantized + scatter segment sums (red.v4) + loss
// ============================================================
__global__ void __launch_bounds__(128)
k_scatter(const float* __restrict__ inputs,
          const float* __restrict__ embedding,
          float* __restrict__ out) {
    __shared__ float xs[C_ * 128];
    float4* xs4 = (float4*)xs;

    int tid = threadIdx.x;
    int b  = blockIdx.x >> 5;
    int f0 = (blockIdx.x & 31) << 7;

    const float4* inp4 = (const float4*)(inputs + (size_t)b * C_ * F_);
    int f04 = f0 >> 2;
#pragma unroll
    for (int it = tid; it < 2048; it += 128) {
        int k = it >> 5, m4 = it & 31;
        xs4[it] = inp4[k * (F_ / 4) + f04 + m4];
    }
    __syncthreads();

    int t = b * F_ + f0 + tid;
    int idx = g_idx[t];
    const float4* e4 = (const float4*)(embedding + idx * C_);
    float* esum = g_emb_sum + (size_t)idx * C_;

    float lacc = 0.0f;
#pragma unroll
    for (int c4 = 0; c4 < 16; c4++) {
        float4 q = e4[c4];
        float qv[4] = {q.x, q.y, q.z, q.w};
        float xv[4];
#pragma unroll
        for (int l = 0; l < 4; l++) {
            int c = c4 * 4 + l;
            float x = xs[c * 128 + tid];
            xv[l] = x;
            float d = x - qv[l];
            lacc = fmaf(d, d, lacc);
            xs[c * 128 + tid] = qv[l];
        }
        red_add_v4(&esum[c4 * 4], xv[0], xv[1], xv[2], xv[3]);
    }
    atomicAdd(&g_cs[idx], 1.0f);
    out[OFF_IDX + t] = (float)idx;

#pragma unroll
    for (int off = 16; off > 0; off >>= 1)
        lacc += __shfl_down_sync(0xffffffffu, lacc, off);
    if ((tid & 31) == 0) atomicAdd(&g_loss, lacc);

    __syncthreads();
    float4* out4 = (float4*)(out + OFF_Q);
    size_t rowbase = (size_t)b * C_ * F_;
#pragma unroll
    for (int it = tid; it < 2048; it += 128) {
        int c = it >> 5, m4 = it & 31;
        out4[(rowbase + (size_t)c * F_ + f0) / 4 + m4] = xs4[it];
    }
}

// ============================================================
// Kernel 3 (merged EMA)
// ============================================================
__global__ void __launch_bounds__(256)
k_ema(const float* __restrict__ embedding_avg,
      const float* __restrict__ cluster_size,
      float* __restrict__ out) {
    __shared__ float wsum[8];
    __shared__ float s_n;
    int tid = threadIdx.x;

    float s = 0.0f;
#pragma unroll
    for (int k = 0; k < 8; k++) {
        int j = tid + 256 * k;
        s += DECAY_ * cluster_size[j] + OMD_ * g_cs[j];
    }
#pragma unroll
    for (int off = 16; off > 0; off >>= 1)
        s += __shfl_down_sync(0xffffffffu, s, off);
    if ((tid & 31) == 0) wsum[tid >> 5] = s;
    __syncthreads();
    if (tid == 0) {
        float n = 0.0f;
#pragma unroll
        for (int w = 0; w < 8; w++) n += wsum[w];
        s_n = n;
    }
    __syncthreads();
    float n = s_n;
    float denom = n + (float)SIZE_ * EPS_;
    float mn = fmaxf(n, 1.0f);

    if (blockIdx.x == 0) {
#pragma unroll
        for (int k = 0; k < 8; k++) {
            int j = tid + 256 * k;
            out[OFF_NCS + j] = DECAY_ * cluster_size[j] + OMD_ * g_cs[j];
        }
        if (tid == 0)
            out[OFF_LOSS] = g_loss * (1.0f / (float)(N_ * C_));
    }

    int i = blockIdx.x * 256 + tid;           // 0..131071
    int row = i >> 6;
    float ncs = DECAY_ * cluster_size[row] + OMD_ * g_cs[row];
    float inv = denom / ((ncs + EPS_) * mn);
    float nea = DECAY_ * embedding_avg[i] + OMD_ * g_emb_sum[i];
    out[OFF_NEA + i]  = nea;
    out[OFF_NEMB + i] = nea * inv;
}

// ============================================================
extern "C" void kernel_launch(void* const* d_in, const int* in_sizes, int n_in,
                              void* d_out, int out_size) {
    const float* inputs        = (const float*)d_in[0];
    const float* embedding     = (const float*)d_in[1];
    const float* embedding_avg = (const float*)d_in[2];
    const float* cluster_size  = (const float*)d_in[3];
    float* out = (float*)d_out;

    cudaFuncSetAttribute(k_argmin_mma, cudaFuncAttributeMaxDynamicSharedMemorySize, SM_TOT);

    k_init<<<512, 256>>>(embedding);
    k_argmin_mma<<<1024, 256, SM_TOT>>>(inputs);
    k_scatter<<<1024, 128>>>(inputs, embedding, out);
    k_ema<<<512, 256>>>(embedding_avg, cluster_size, out);
}